// round 1
// baseline (speedup 1.0000x reference)
#include <cuda_runtime.h>
#include <cuda_bf16.h>

// Problem constants
#define NC       8
#define CIN      512
#define COUT     256
#define CIN_SUB  64    // CIN / NC
#define COUT_SUB 32    // COUT / NC
#define HI       64
#define HO       128
#define BATCH    8
#define KSZ      4

// Cayley-Dickson component-index table (abs of comp mat), derived from the
// reference's signed recursion (NOT i^j because signs are folded in before abs).
__constant__ int c_IDX[8][8] = {
    {0,1,2,1,4,3,2,3},
    {1,0,3,2,5,4,1,2},
    {2,1,0,1,6,5,4,3},
    {3,2,1,0,7,6,5,4},
    {4,3,2,3,0,1,2,1},
    {5,4,1,2,1,0,3,2},
    {6,5,4,3,2,1,0,1},
    {7,6,5,4,3,2,1,0}};
// sign[i][j] = (j <= i) ? +1 : -1   (verified against the reference recursion)

// Scratch: fused big weight, laid out [kh][kw][ci=512][co=256] for coalesced
// co-contiguous reads in the conv kernel. 16*512*256*4B = 8 MB.
__device__ float g_Wt[16 * CIN * COUT];
__device__ float g_bias[COUT];

// ---------------------------------------------------------------------------
// Prep: Wt[kh][kw][j*64+a][i*32+c] = sign(i,j) * W[idx(i,j)][a][c][kh][kw]
// W input layout: [8][64][32][4][4]
// ---------------------------------------------------------------------------
__global__ void build_weight_kernel(const float* __restrict__ W) {
    int e = blockIdx.x * blockDim.x + threadIdx.x;   // 16*512*256 total
    if (e >= 16 * CIN * COUT) return;
    int co  = e & 255;
    int ci  = (e >> 8) & 511;
    int kwh = e >> 17;          // 0..15
    int kh = kwh >> 2, kw = kwh & 3;
    int i = co >> 5, c = co & 31;   // output component, sub-channel
    int j = ci >> 6, a = ci & 63;   // input component, sub-channel
    float sgn  = (j <= i) ? 1.0f : -1.0f;
    int comp = c_IDX[i][j];
    float v = W[(((comp * CIN_SUB + a) * COUT_SUB + c) * 16) + kh * 4 + kw];
    g_Wt[e] = sgn * v;
}

// bias_big[i*32+c] = sum_j sign(i,j) * b[idx(i,j)][c]
__global__ void build_bias_kernel(const float* __restrict__ b) {
    int t = threadIdx.x;
    if (t >= COUT) return;
    int i = t >> 5, c = t & 31;
    float s = 0.f;
#pragma unroll
    for (int j = 0; j < 8; ++j) {
        float sgn = (j <= i) ? 1.0f : -1.0f;
        s += sgn * b[c_IDX[i][j] * COUT_SUB + c];
    }
    g_bias[t] = s;
}

// ---------------------------------------------------------------------------
// Main conv kernel.
// Parity decomposition: out[2y'+py][2x'+px] = bias[co] +
//   sum_ci sum_{t,u in {0,1}} x[ci][y'-1+py+t][x'-1+px+u] *
//                             Wt[kh=3-py-2t][kw=3-px-2u][ci][co]
// Block: 64 co x 64 x' (one output row y', one parity, one batch).
// 128 threads: 8 co-threads x 16 px-threads; each thread 8co x 4px accs.
// K loop: ci in chunks of 8 through shared memory.
// ---------------------------------------------------------------------------
__global__ __launch_bounds__(128)
void hconvt_kernel(const float* __restrict__ x, float* __restrict__ out) {
    const int co0 = blockIdx.x * 64;          // 0,64,128,192
    const int yp  = blockIdx.y;               // y' in [0,64)
    const int z   = blockIdx.z;               // [0,32): b*4 + py*2 + px
    const int b   = z >> 2;
    const int py  = (z >> 1) & 1;
    const int px  = z & 1;

    const int tid = threadIdx.x;
    const int tpx = tid & 15;                 // px-thread  -> x' = tpx*4..+3
    const int tco = tid >> 4;                 // co-thread  -> co = tco*8..+7
    const int p0  = tpx * 4;
    const int co_l = tco * 8;

    __shared__ float Xs[8][2][66];            // [ci][t(row)][col = x'+u, 0..64]
    __shared__ float Ws[8][2][2][64];         // [ci][t][u][co]

    float acc[8][4];
#pragma unroll
    for (int k = 0; k < 8; ++k)
#pragma unroll
        for (int i = 0; i < 4; ++i) acc[k][i] = 0.f;

    const int iy0 = yp - 1 + py;              // row for t=0

    for (int cc = 0; cc < CIN; cc += 8) {
        // --- load input tile (with halo + zero OOB) ---
        for (int i = tid; i < 8 * 2 * 66; i += 128) {
            int col = i % 66;
            int t   = (i / 66) & 1;
            int cl  = i / 132;
            float v = 0.f;
            int ix = col + px - 1;
            int iy = iy0 + t;
            if (col < 65 && (unsigned)ix < HI && (unsigned)iy < HI)
                v = x[(((b * CIN + cc + cl) * HI) + iy) * HI + ix];
            Xs[cl][t][col] = v;
        }
        // --- load weight tile ---
        for (int i = tid; i < 8 * 2 * 2 * 64; i += 128) {
            int co = i & 63;
            int u  = (i >> 6) & 1;
            int t  = (i >> 7) & 1;
            int cl = i >> 8;
            int kh = 3 - py - 2 * t;
            int kw = 3 - px - 2 * u;
            Ws[cl][t][u][co] =
                g_Wt[((kh * 4 + kw) * CIN + cc + cl) * COUT + co0 + co];
        }
        __syncthreads();

#pragma unroll
        for (int cl = 0; cl < 8; ++cl) {
            float xv[2][5];
#pragma unroll
            for (int t = 0; t < 2; ++t)
#pragma unroll
                for (int i = 0; i < 5; ++i) xv[t][i] = Xs[cl][t][p0 + i];
#pragma unroll
            for (int t = 0; t < 2; ++t) {
#pragma unroll
                for (int u = 0; u < 2; ++u) {
                    float wv[8];
#pragma unroll
                    for (int k = 0; k < 8; ++k) wv[k] = Ws[cl][t][u][co_l + k];
#pragma unroll
                    for (int k = 0; k < 8; ++k)
#pragma unroll
                        for (int i = 0; i < 4; ++i)
                            acc[k][i] = fmaf(wv[k], xv[t][u + i], acc[k][i]);
                }
            }
        }
        __syncthreads();
    }

    // --- epilogue: add bias, scatter to strided output positions ---
    const int oy = 2 * yp + py;
#pragma unroll
    for (int k = 0; k < 8; ++k) {
        const int co = co0 + co_l + k;
        const float bias = g_bias[co];
        float* orow = out + (((long)b * COUT + co) * HO + oy) * HO;
#pragma unroll
        for (int i = 0; i < 4; ++i) {
            int ox = 2 * (p0 + i) + px;
            orow[ox] = acc[k][i] + bias;
        }
    }
}

// ---------------------------------------------------------------------------
extern "C" void kernel_launch(void* const* d_in, const int* in_sizes, int n_in,
                              void* d_out, int out_size) {
    const float* x = (const float*)d_in[0];   // [8,512,64,64]
    const float* W = (const float*)d_in[1];   // [8,64,32,4,4]
    const float* b = (const float*)d_in[2];   // [8,32]
    float* out = (float*)d_out;               // [8,256,128,128]

    build_weight_kernel<<<(16 * CIN * COUT + 255) / 256, 256>>>(W);
    build_bias_kernel<<<1, 256>>>(b);

    dim3 grid(COUT / 64, HI, BATCH * 4);      // (4, 64, 32)
    hconvt_kernel<<<grid, 128>>>(x, out);
}

// round 5
// speedup vs baseline: 7.0137x; 7.0137x over previous
#include <cuda_runtime.h>
#include <cuda_fp16.h>
#include <cstdint>

// ---------------------------------------------------------------------------
// HyperTransposeConv via fp16 mma.sync implicit GEMM (sm_80 PTX, fallback
// HMMA on sm_103 — tcgen05 PTX is not available under compute_103).
//
// Parity decomposition (validated R1):
//   out[b][co][2y'+py][2x'+px] = bias[co] +
//     sum_{ci,t,u} x[b][ci][y'-1+py+t][x'+px-1+u] * Wt[3-py-2t][3-px-2u][ci][co]
// GEMM per (b,par): C[m=co][n=pixel], K = 2048 flattened (ci,t,u).
// CTA tile 128x128, K-chunks of 32, 8 warps (4m x 2n), warp tile 32x64.
// ---------------------------------------------------------------------------

#define CIN  512
#define COUT 256
#define HIN  64
#define HOUT 128

__constant__ int c_IDX[8][8] = {
    {0,1,2,1,4,3,2,3},
    {1,0,3,2,5,4,1,2},
    {2,1,0,1,6,5,4,3},
    {3,2,1,0,7,6,5,4},
    {4,3,2,3,0,1,2,1},
    {5,4,1,2,1,0,3,2},
    {6,5,4,3,2,1,0,1},
    {7,6,5,4,3,2,1,0}};
// sign[i][j] = (j <= i) ? +1 : -1

// W packed per parity: [par][co 256][k 2048] fp16 (4 MB)
__device__ __half g_Wh[4u * 256 * 2048];
// x converted to fp16: [b][ci][64][64] (33.5 MB)
__device__ __half g_xh[8u * 512 * 64 * 64];
__device__ float g_bias[COUT];

// ---------------------------------------------------------------------------
__global__ void build_wh(const float* __restrict__ W) {
    int e = blockIdx.x * 256 + threadIdx.x;
    if (e >= 4 * 256 * 2048) return;
    int k   = e & 2047;
    int co  = (e >> 11) & 255;
    int par = e >> 19;
    int py = par >> 1, px = par & 1;
    int u = k & 1, t = (k >> 1) & 1, ci = k >> 2;
    int i = co >> 5, c = co & 31;
    int j = ci >> 6, a = ci & 63;
    int kh = 3 - py - 2 * t, kw = 3 - px - 2 * u;
    float sgn = (j <= i) ? 1.0f : -1.0f;
    g_Wh[e] = __float2half_rn(
        sgn * W[((c_IDX[i][j] * 64 + a) * 32 + c) * 16 + kh * 4 + kw]);
}

__global__ void build_bias(const float* __restrict__ b) {
    int t = threadIdx.x;
    if (t >= COUT) return;
    int i = t >> 5, c = t & 31;
    float s = 0.f;
#pragma unroll
    for (int j = 0; j < 8; ++j)
        s += ((j <= i) ? 1.0f : -1.0f) * b[c_IDX[i][j] * 32 + c];
    g_bias[t] = s;
}

__global__ void conv_x(const float* __restrict__ x) {
    int e = blockIdx.x * 256 + threadIdx.x;   // 4,194,304 float4 groups
    float4 v = reinterpret_cast<const float4*>(x)[e];
    __half2* d = reinterpret_cast<__half2*>(g_xh);
    d[e * 2]     = __floats2half2_rn(v.x, v.y);
    d[e * 2 + 1] = __floats2half2_rn(v.z, v.w);
}

// ---------------------------------------------------------------------------
#define AST 10240                 // one A stage: 128 rows x 80B
#define BSTG 10240                // one B stage
#define BOFF 30720                // 3 A stages then 2 B stages
#define SMEM_REQ (30720 + 2 * 10240)   // 51200

#define LDSM4(R0, R1, R2, R3, ADDR)                                          \
    asm volatile("ldmatrix.sync.aligned.m8n8.x4.shared.b16 {%0,%1,%2,%3}, [%4];" \
                 : "=r"(R0), "=r"(R1), "=r"(R2), "=r"(R3) : "r"(ADDR))

#define MMA16816(C, A, B0v, B1v)                                             \
    asm volatile("mma.sync.aligned.m16n8k16.row.col.f32.f16.f16.f32 "        \
                 "{%0,%1,%2,%3}, {%4,%5,%6,%7}, {%8,%9}, {%0,%1,%2,%3};"     \
                 : "+f"((C)[0]), "+f"((C)[1]), "+f"((C)[2]), "+f"((C)[3])    \
                 : "r"((A)[0]), "r"((A)[1]), "r"((A)[2]), "r"((A)[3]),       \
                   "r"(B0v), "r"(B1v))

#define CPASYNC16(DST, SRC)                                                  \
    asm volatile("cp.async.cg.shared.global [%0], [%1], 16;"                 \
                 :: "r"(DST), "l"(SRC))

__global__ __launch_bounds__(256, 2)
void hconv_hmma(float* __restrict__ out) {
    extern __shared__ char smem[];
    uint32_t sb;
    asm("{ .reg .u64 t; cvta.to.shared.u64 t, %1; cvt.u32.u64 %0, t; }"
        : "=r"(sb) : "l"(smem));
    const uint32_t Abase = sb, Bbase = sb + BOFF;

    const int tid = threadIdx.x;
    const int l   = tid & 31, wid = tid >> 5;
    const int co0 = blockIdx.x * 128;
    const int y0  = blockIdx.y * 2;          // two y' rows per CTA
    const int z   = blockIdx.z;
    const int b   = z >> 2;
    const int par = z & 3, py = par >> 1, px = par & 1;

    // ---- B-fill thread mapping: n = tid&127, tap-row h = tid>>7 ----
    const int n   = tid & 127;
    const int h   = tid >> 7;
    const int yy  = n >> 6, xq = n & 63;
    const int iy  = y0 + yy - 1 + py + h;
    const int ix0 = xq + px - 1;
    const bool vy = (unsigned)iy < HIN;
    const bool v0 = vy && ((unsigned)ix0 < HIN);
    const bool v1 = vy && ((unsigned)(ix0 + 1) < HIN);
    const int iyc = vy ? iy : 0;
    const __half* xb = g_xh + ((size_t)b * CIN * 4096) + (size_t)iyc * 64 + ix0;
    const uint32_t bsts = Bbase + (uint32_t)(n * 80 + h * 4);

    // ---- A cp.async mapping: rows tid>>2 and tid>>2 + 64, sub = tid&3 ----
    const int arow = tid >> 2, asub = tid & 3;
    const __half* wsrc = g_Wh + ((size_t)(par * 256 + co0 + arow)) * 2048 + asub * 8;
    const uint32_t adst = Abase + (uint32_t)(arow * 80 + asub * 16);

    // warp tiles
    const int m0 = (wid >> 1) * 32;
    const int n0 = (wid & 1) * 64;
    const uint32_t loff = (uint32_t)((l & 15) * 80 + (l >> 4) * 16);

    float acc[2][8][4];
#pragma unroll
    for (int a = 0; a < 2; ++a)
#pragma unroll
        for (int f = 0; f < 8; ++f)
#pragma unroll
            for (int e = 0; e < 4; ++e) acc[a][f][e] = 0.f;

    uint32_t bv[8];

    // ---------------- prologue ----------------
    // fill B(0) regs
#pragma unroll
    for (int j = 0; j < 8; ++j) {
        const __half* p = xb + (size_t)j * 4096;
        unsigned short s0 = 0, s1 = 0;
        if (v0) s0 = *(const unsigned short*)p;
        if (v1) s1 = *(const unsigned short*)(p + 1);
        bv[j] = (uint32_t)s0 | ((uint32_t)s1 << 16);
    }
    // STS B(0) into stage 0
#pragma unroll
    for (int j = 0; j < 8; ++j)
        asm volatile("st.shared.b32 [%0], %1;" :: "r"(bsts + j * 8), "r"(bv[j]) : "memory");
    // cp.async A(0) stage0, A(1) stage1
#pragma unroll
    for (int e = 0; e < 2; ++e)
        CPASYNC16(adst + e * (64 * 80), wsrc + (size_t)e * 64 * 2048);
    asm volatile("cp.async.commit_group;");
#pragma unroll
    for (int e = 0; e < 2; ++e)
        CPASYNC16(adst + AST + e * (64 * 80), wsrc + (size_t)e * 64 * 2048 + 32);
    asm volatile("cp.async.commit_group;");
    // fill B(1) regs
#pragma unroll
    for (int j = 0; j < 8; ++j) {
        const __half* p = xb + (size_t)(8 + j) * 4096;
        unsigned short s0 = 0, s1 = 0;
        if (v0) s0 = *(const unsigned short*)p;
        if (v1) s1 = *(const unsigned short*)(p + 1);
        bv[j] = (uint32_t)s0 | ((uint32_t)s1 << 16);
    }

    // ---------------- main loop over 64 K-chunks ----------------
#pragma unroll 1
    for (int i = 0; i < 64; ++i) {
        asm volatile("cp.async.wait_group 1;");
        __syncthreads();

        // prefetch A(i+2) into stage (i+2)%3  (reads of that stage ended i-1)
        if (i + 2 < 64) {
            const int st = (i + 2) % 3;
            const __half* s = wsrc + (i + 2) * 32;
#pragma unroll
            for (int e = 0; e < 2; ++e)
                CPASYNC16(adst + st * AST + e * (64 * 80), s + (size_t)e * 64 * 2048);
        }
        asm volatile("cp.async.commit_group;");

        // STS B(i+1) into stage (i+1)&1
        if (i + 1 < 64) {
            const uint32_t bs = bsts + ((i + 1) & 1) * BSTG;
#pragma unroll
            for (int j = 0; j < 8; ++j)
                asm volatile("st.shared.b32 [%0], %1;" :: "r"(bs + j * 8), "r"(bv[j]) : "memory");
        }
        // fill B(i+2) regs (LDG latency hidden behind mma below)
        if (i + 2 < 64) {
            const __half* pc = xb + (size_t)(i + 2) * 8 * 4096;
#pragma unroll
            for (int j = 0; j < 8; ++j) {
                const __half* p = pc + (size_t)j * 4096;
                unsigned short s0 = 0, s1 = 0;
                if (v0) s0 = *(const unsigned short*)p;
                if (v1) s1 = *(const unsigned short*)(p + 1);
                bv[j] = (uint32_t)s0 | ((uint32_t)s1 << 16);
            }
        }

        // ---- mma on chunk i ----
        const uint32_t As = Abase + (i % 3) * AST;
        const uint32_t Bs = Bbase + (i & 1) * BSTG;
#pragma unroll
        for (int ks = 0; ks < 2; ++ks) {
            uint32_t af[2][4];
#pragma unroll
            for (int mm = 0; mm < 2; ++mm)
                LDSM4(af[mm][0], af[mm][1], af[mm][2], af[mm][3],
                      As + (uint32_t)((m0 + mm * 16) * 80 + ks * 32) + loff);
            uint32_t bf[8][2];
#pragma unroll
            for (int nb = 0; nb < 4; ++nb) {
                uint32_t r0, r1, r2, r3;
                LDSM4(r0, r1, r2, r3,
                      Bs + (uint32_t)((n0 + nb * 16) * 80 + ks * 32) + loff);
                bf[nb * 2][0] = r0; bf[nb * 2][1] = r2;
                bf[nb * 2 + 1][0] = r1; bf[nb * 2 + 1][1] = r3;
            }
#pragma unroll
            for (int mm = 0; mm < 2; ++mm)
#pragma unroll
                for (int f = 0; f < 8; ++f)
                    MMA16816(acc[mm][f], af[mm], bf[f][0], bf[f][1]);
        }
    }

    // ---------------- epilogue ----------------
#pragma unroll
    for (int mm = 0; mm < 2; ++mm) {
#pragma unroll
        for (int eh = 0; eh < 2; ++eh) {
            const int m  = m0 + mm * 16 + (l >> 2) + eh * 8;
            const int co = co0 + m;
            const float bias = g_bias[co];
            float* ob = out + ((size_t)(b * COUT + co) * HOUT) * HOUT;
#pragma unroll
            for (int f = 0; f < 8; ++f) {
#pragma unroll
                for (int ew = 0; ew < 2; ++ew) {
                    const int np = n0 + f * 8 + 2 * (l & 3) + ew;
                    const int oy = 2 * (y0 + (np >> 6)) + py;
                    const int ox = 2 * (np & 63) + px;
                    ob[(size_t)oy * HOUT + ox] = acc[mm][f][eh * 2 + ew] + bias;
                }
            }
        }
    }
}

// ---------------------------------------------------------------------------
extern "C" void kernel_launch(void* const* d_in, const int* in_sizes, int n_in,
                              void* d_out, int out_size) {
    const float* x = (const float*)d_in[0];   // [8,512,64,64]
    const float* W = (const float*)d_in[1];   // [8,64,32,4,4]
    const float* b = (const float*)d_in[2];   // [8,32]
    float* out = (float*)d_out;               // [8,256,128,128]

    build_wh<<<(4 * 256 * 2048 + 255) / 256, 256>>>(W);
    build_bias<<<1, 256>>>(b);
    conv_x<<<(8 * 512 * 64 * 64 / 4 + 255) / 256, 256>>>(x);

    cudaFuncSetAttribute(hconv_hmma,
                         cudaFuncAttributeMaxDynamicSharedMemorySize, SMEM_REQ);
    dim3 grid(2, 32, 32);
    hconv_hmma<<<grid, 256, SMEM_REQ>>>(out);
}